// round 14
// baseline (speedup 1.0000x reference)
#include <cuda_runtime.h>
#include <cuda_bf16.h>
#include <stdint.h>

#define NNODE 1000000
#define NEDGE 8000000

// Scratch in __device__ globals (zero-initialized at module load; g_deg is
// re-zeroed by k_final each run -> self-cleaning, no k_zero pass).
__device__ float  g_deg [NNODE];   // in-degree at dst; zeroed in k_final
__device__ float  g_dinv[NNODE];   // rsqrt(deg + 1)
__device__ float4 g_xs  [NNODE];   // x * dinv (gather source for scatter1)
__device__ float4 g_acc1[NNODE];   // layer-1 acc; INIT = xs (self-loop folded in)
__device__ float2 g_gs  [NNODE];   // (relu(.) W2) * dinv (gather source for scatter2)
__device__ float2 g_acc2[NNODE];   // layer-2 acc; INIT = gs (self-loop folded in)

// ---------------------------------------------------------------------------
// PDL intrinsics
__device__ __forceinline__ void pdl_wait() {
    asm volatile("griddepcontrol.wait;" ::: "memory");
}
__device__ __forceinline__ void pdl_trigger() {
    asm volatile("griddepcontrol.launch_dependents;" ::: "memory");
}

__device__ __forceinline__ void red_v4(float4* p, float4 v) {
    asm volatile("red.global.add.v4.f32 [%0], {%1,%2,%3,%4};"
                 :: "l"(p), "f"(v.x), "f"(v.y), "f"(v.z), "f"(v.w) : "memory");
}
__device__ __forceinline__ void red_v2(float2* p, float2 v) {
    asm volatile("red.global.add.v2.f32 [%0], {%1,%2};"
                 :: "l"(p), "f"(v.x), "f"(v.y) : "memory");
}
__device__ __forceinline__ float4 ldcg_f4(const float4* p) { return __ldcg(p); }
__device__ __forceinline__ float2 ldcg_f2(const float2* p) { return __ldcg(p); }

// packed f32x2 helpers (sm_103a FFMA2 path)
#define PACK2(out, lo, hi) \
    asm("mov.b64 %0, {%1, %2};" : "=l"(out) : "f"(lo), "f"(hi))
#define UNPACK2(lo, hi, in) \
    asm("mov.b64 {%0, %1}, %2;" : "=f"(lo), "=f"(hi) : "l"(in))
#define FMA2(d, a, b, c) \
    asm("fma.rn.f32x2 %0, %1, %2, %3;" : "=l"(d) : "l"(a), "l"(b), "l"(c))

// ---------------------------------------------------------------------------
// 1. in-degree at dst — 4 edges/thread
__global__ void __launch_bounds__(256) k_deg(const int* __restrict__ dst, int e) {
    pdl_wait();
    int base = (blockIdx.x * blockDim.x + threadIdx.x) * 4;
    if (base + 4 <= e) {
        int4 d = *(const int4*)(dst + base);
        atomicAdd(&g_deg[d.x], 1.0f);
        atomicAdd(&g_deg[d.y], 1.0f);
        atomicAdd(&g_deg[d.z], 1.0f);
        atomicAdd(&g_deg[d.w], 1.0f);
    } else {
        for (int i = base; i < e; i++) atomicAdd(&g_deg[dst[i]], 1.0f);
    }
    pdl_trigger();
}

// ---------------------------------------------------------------------------
// 2. dinv + pre-scaled features; acc1 INITIALIZED to xs (self-loop term)
__global__ void __launch_bounds__(256) k_prep(const float4* __restrict__ x, int n) {
    pdl_wait();
    int i = blockIdx.x * blockDim.x + threadIdx.x;
    if (i < n) {
        float di = rsqrtf(g_deg[i] + 1.0f);   // self-loop -> deg >= 1
        g_dinv[i] = di;
        float4 v = x[i];
        v.x *= di; v.y *= di; v.z *= di; v.w *= di;
        g_xs[i]   = v;
        g_acc1[i] = v;   // self-loop contribution pre-seeded
    }
    pdl_trigger();
}

// ---------------------------------------------------------------------------
// 3. layer-1 scatter: acc1[dst] += xs[src] — 4 edges/thread
__global__ void __launch_bounds__(256) k_scatter1(const int* __restrict__ src,
                                                  const int* __restrict__ dst, int e) {
    pdl_wait();
    int base = (blockIdx.x * blockDim.x + threadIdx.x) * 4;
    if (base + 4 <= e) {
        int4 s = *(const int4*)(src + base);
        int4 d = *(const int4*)(dst + base);
        float4 v0 = ldcg_f4(&g_xs[s.x]);
        float4 v1 = ldcg_f4(&g_xs[s.y]);
        float4 v2 = ldcg_f4(&g_xs[s.z]);
        float4 v3 = ldcg_f4(&g_xs[s.w]);
        red_v4(&g_acc1[d.x], v0);
        red_v4(&g_acc1[d.y], v1);
        red_v4(&g_acc1[d.z], v2);
        red_v4(&g_acc1[d.w], v3);
    } else {
        for (int i = base; i < e; i++)
            red_v4(&g_acc1[dst[i]], ldcg_f4(&g_xs[src[i]]));
    }
    pdl_trigger();
}

// ---------------------------------------------------------------------------
// 4. fused node transform (1 node/thread; j-pairs in f32x2 lanes; weights
//    PRE-PACKED in smem as {w_j, w_j+1} u64 pairs -> ZERO in-loop packs):
//    a4 = dinv * acc1          (acc1 already includes self-loop)
//    gs = (relu(a4 W1 + b1) W2) * dinv
//    acc2 INITIALIZED to gs    (layer-2 self-loop term pre-seeded)
__global__ void __launch_bounds__(256) k_mid(const float* __restrict__ W1,   // [4,64]
                                             const float* __restrict__ b1,   // [64]
                                             const float* __restrict__ W2,   // [64,2]
                                             int n) {
    __shared__ ulonglong2         sU[32];  // { {W1[0][j],W1[0][j+1]}, {W1[1][j],W1[1][j+1]} }
    __shared__ ulonglong2         sV[32];  // { {W1[2][j],W1[2][j+1]}, {W1[3][j],W1[3][j+1]} }
    __shared__ ulonglong2         sWp[32]; // { {b1[j],b1[j+1]}, {W2[j][0],W2[j+1][0]} }
    __shared__ unsigned long long sX[32];  // { {W2[j][1],W2[j+1][1]} }
    int t = threadIdx.x;
    if (t < 32) {
        int j = 2 * t;
        unsigned long long u0, u1, v0, v1, wb, wc, wd;
        PACK2(u0, W1[j],       W1[j + 1]);
        PACK2(u1, W1[64 + j],  W1[64 + j + 1]);
        PACK2(v0, W1[128 + j], W1[128 + j + 1]);
        PACK2(v1, W1[192 + j], W1[192 + j + 1]);
        PACK2(wb, b1[j],       b1[j + 1]);
        PACK2(wc, W2[2 * j],   W2[2 * j + 2]);
        PACK2(wd, W2[2 * j + 1], W2[2 * j + 3]);
        sU[t]  = make_ulonglong2(u0, u1);
        sV[t]  = make_ulonglong2(v0, v1);
        sWp[t] = make_ulonglong2(wb, wc);
        sX[t]  = wd;
    }
    pdl_wait();
    __syncthreads();

    int i = blockIdx.x * blockDim.x + t;
    if (i >= n) return;

    float di = g_dinv[i];
    float4 a = g_acc1[i];
    float a0 = di * a.x;
    float a1 = di * a.y;
    float a2 = di * a.z;
    float a3 = di * a.w;

    unsigned long long pa0, pa1, pa2, pa3, po0, po1;
    PACK2(pa0, a0, a0);
    PACK2(pa1, a1, a1);
    PACK2(pa2, a2, a2);
    PACK2(pa3, a3, a3);
    PACK2(po0, 0.f, 0.f);
    PACK2(po1, 0.f, 0.f);

#pragma unroll
    for (int j2 = 0; j2 < 32; j2++) {
        ulonglong2 U = sU[j2];
        ulonglong2 V = sV[j2];
        ulonglong2 Wp = sWp[j2];
        unsigned long long X = sX[j2];
        unsigned long long h2 = Wp.x;         // {b1[j], b1[j+1]}
        FMA2(h2, pa0, U.x, h2);
        FMA2(h2, pa1, U.y, h2);
        FMA2(h2, pa2, V.x, h2);
        FMA2(h2, pa3, V.y, h2);
        float hl, hh;
        UNPACK2(hl, hh, h2);                  // reg-pair alias, ~free
        hl = fmaxf(hl, 0.f);
        hh = fmaxf(hh, 0.f);
        PACK2(h2, hl, hh);
        FMA2(po0, h2, Wp.y, po0);             // o0 += h * W2[.][0]
        FMA2(po1, h2, X,    po1);             // o1 += h * W2[.][1]
    }
    float p0l, p0h, p1l, p1h;
    UNPACK2(p0l, p0h, po0);
    UNPACK2(p1l, p1h, po1);
    float2 gs = make_float2((p0l + p0h) * di, (p1l + p1h) * di);

    g_gs[i]   = gs;
    g_acc2[i] = gs;   // self-loop contribution pre-seeded
    pdl_trigger();
}

// ---------------------------------------------------------------------------
// 5. layer-2 scatter: acc2[dst] += gs[src] — 4 edges/thread
__global__ void __launch_bounds__(256) k_scatter2(const int* __restrict__ src,
                                                  const int* __restrict__ dst, int e) {
    pdl_wait();
    int base = (blockIdx.x * blockDim.x + threadIdx.x) * 4;
    if (base + 4 <= e) {
        int4 s = *(const int4*)(src + base);
        int4 d = *(const int4*)(dst + base);
        float2 v0 = ldcg_f2(&g_gs[s.x]);
        float2 v1 = ldcg_f2(&g_gs[s.y]);
        float2 v2 = ldcg_f2(&g_gs[s.z]);
        float2 v3 = ldcg_f2(&g_gs[s.w]);
        red_v2(&g_acc2[d.x], v0);
        red_v2(&g_acc2[d.y], v1);
        red_v2(&g_acc2[d.z], v2);
        red_v2(&g_acc2[d.w], v3);
    } else {
        for (int i = base; i < e; i++)
            red_v2(&g_acc2[dst[i]], ldcg_f2(&g_gs[src[i]]));
    }
    pdl_trigger();
}

// ---------------------------------------------------------------------------
// 6. final: out = dinv * acc2 + b2 (acc2 already includes self-loop);
//    re-zeroes deg for the next run
__global__ void __launch_bounds__(256) k_final(const float* __restrict__ b2,
                                               float2* __restrict__ out, int n) {
    float bx = __ldg(&b2[0]);
    float by = __ldg(&b2[1]);
    pdl_wait();
    int i = blockIdx.x * blockDim.x + threadIdx.x;
    if (i < n) {
        float di = g_dinv[i];
        float2 a = g_acc2[i];
        out[i] = make_float2(di * a.x + bx, di * a.y + by);
        g_deg[i] = 0.0f;   // self-clean: ready for next invocation/replay
    }
}

// ---------------------------------------------------------------------------
// PDL launch helper
template <typename... Args>
static void pdl_launch(void (*kern)(Args...), int grid, int block,
                       Args... args) {
    cudaLaunchConfig_t cfg = {};
    cfg.gridDim  = dim3(grid, 1, 1);
    cfg.blockDim = dim3(block, 1, 1);
    cfg.dynamicSmemBytes = 0;
    cfg.stream = 0;
    cudaLaunchAttribute attr[1];
    attr[0].id = cudaLaunchAttributeProgrammaticStreamSerialization;
    attr[0].val.programmaticStreamSerializationAllowed = 1;
    cfg.attrs = attr;
    cfg.numAttrs = 1;
    cudaLaunchKernelEx(&cfg, kern, args...);
}

extern "C" void kernel_launch(void* const* d_in, const int* in_sizes, int n_in,
                              void* d_out, int out_size) {
    const float* x  = (const float*)d_in[0];   // [N,4]
    const int*   ei = (const int*)d_in[1];     // [2,E]  int32
    const float* W1 = (const float*)d_in[2];   // [4,64]
    const float* b1 = (const float*)d_in[3];   // [64]
    const float* W2 = (const float*)d_in[4];   // [64,2]
    const float* b2 = (const float*)d_in[5];   // [2]
    float2*      out = (float2*)d_out;         // [N,2]

    const int n = in_sizes[0] / 4;
    const int e = in_sizes[1] / 2;
    const int* src = ei;
    const int* dst = ei + e;

    const int T = 256;
    const int gn  = (n + T - 1) / T;
    const int ge4 = ((e + 3) / 4 + T - 1) / T;   // 4 edges/thread

    pdl_launch(k_deg,      ge4, T, dst, e);
    pdl_launch(k_prep,     gn,  T, (const float4*)x, n);
    pdl_launch(k_scatter1, ge4, T, src, dst, e);
    pdl_launch(k_mid,      gn,  T, W1, b1, W2, n);
    pdl_launch(k_scatter2, ge4, T, src, dst, e);
    pdl_launch(k_final,    gn,  T, b2, out, n);
}

// round 15
// speedup vs baseline: 1.0198x; 1.0198x over previous
#include <cuda_runtime.h>
#include <cuda_bf16.h>
#include <stdint.h>

#define NNODE 1000000
#define NEDGE 8000000

// Scratch in __device__ globals (zero-initialized at module load; g_deg is
// re-zeroed by k_final each run -> self-cleaning, no k_zero pass).
__device__ float  g_deg [NNODE];   // in-degree at dst; zeroed in k_final
__device__ float  g_dinv[NNODE];   // rsqrt(deg + 1)
__device__ float4 g_xs  [NNODE];   // x * dinv (gather source for scatter1)
__device__ float4 g_acc1[NNODE];   // layer-1 acc; INIT = xs (self-loop folded in)
__device__ float2 g_gs  [NNODE];   // (relu(.) W2) * dinv (gather source for scatter2)
__device__ float2 g_acc2[NNODE];   // layer-2 acc; INIT = gs (self-loop folded in)

// Weights in constant memory: uniform accesses go through the LDCU path
// (uniform-register port, floor 1/cyc) instead of the LDS crossbar (floor 4).
__constant__ float c_W1[256];   // [4,64] row-major
__constant__ float c_b1[64];
__constant__ float c_W2[128];   // [64,2] row-major

// ---------------------------------------------------------------------------
// PDL intrinsics
__device__ __forceinline__ void pdl_wait() {
    asm volatile("griddepcontrol.wait;" ::: "memory");
}
__device__ __forceinline__ void pdl_trigger() {
    asm volatile("griddepcontrol.launch_dependents;" ::: "memory");
}

__device__ __forceinline__ void red_v4(float4* p, float4 v) {
    asm volatile("red.global.add.v4.f32 [%0], {%1,%2,%3,%4};"
                 :: "l"(p), "f"(v.x), "f"(v.y), "f"(v.z), "f"(v.w) : "memory");
}
__device__ __forceinline__ void red_v2(float2* p, float2 v) {
    asm volatile("red.global.add.v2.f32 [%0], {%1,%2};"
                 :: "l"(p), "f"(v.x), "f"(v.y) : "memory");
}
__device__ __forceinline__ float4 ldcg_f4(const float4* p) { return __ldcg(p); }
__device__ __forceinline__ float2 ldcg_f2(const float2* p) { return __ldcg(p); }

// ---------------------------------------------------------------------------
// 1. in-degree at dst — 4 edges/thread
__global__ void __launch_bounds__(256) k_deg(const int* __restrict__ dst, int e) {
    pdl_wait();
    int base = (blockIdx.x * blockDim.x + threadIdx.x) * 4;
    if (base + 4 <= e) {
        int4 d = *(const int4*)(dst + base);
        atomicAdd(&g_deg[d.x], 1.0f);
        atomicAdd(&g_deg[d.y], 1.0f);
        atomicAdd(&g_deg[d.z], 1.0f);
        atomicAdd(&g_deg[d.w], 1.0f);
    } else {
        for (int i = base; i < e; i++) atomicAdd(&g_deg[dst[i]], 1.0f);
    }
    pdl_trigger();
}

// ---------------------------------------------------------------------------
// 2. dinv + pre-scaled features; acc1 INITIALIZED to xs (self-loop term)
__global__ void __launch_bounds__(256) k_prep(const float4* __restrict__ x, int n) {
    pdl_wait();
    int i = blockIdx.x * blockDim.x + threadIdx.x;
    if (i < n) {
        float di = rsqrtf(g_deg[i] + 1.0f);   // self-loop -> deg >= 1
        g_dinv[i] = di;
        float4 v = x[i];
        v.x *= di; v.y *= di; v.z *= di; v.w *= di;
        g_xs[i]   = v;
        g_acc1[i] = v;   // self-loop contribution pre-seeded
    }
    pdl_trigger();
}

// ---------------------------------------------------------------------------
// 3. layer-1 scatter: acc1[dst] += xs[src] — 4 edges/thread
__global__ void __launch_bounds__(256) k_scatter1(const int* __restrict__ src,
                                                  const int* __restrict__ dst, int e) {
    pdl_wait();
    int base = (blockIdx.x * blockDim.x + threadIdx.x) * 4;
    if (base + 4 <= e) {
        int4 s = *(const int4*)(src + base);
        int4 d = *(const int4*)(dst + base);
        float4 v0 = ldcg_f4(&g_xs[s.x]);
        float4 v1 = ldcg_f4(&g_xs[s.y]);
        float4 v2 = ldcg_f4(&g_xs[s.z]);
        float4 v3 = ldcg_f4(&g_xs[s.w]);
        red_v4(&g_acc1[d.x], v0);
        red_v4(&g_acc1[d.y], v1);
        red_v4(&g_acc1[d.z], v2);
        red_v4(&g_acc1[d.w], v3);
    } else {
        for (int i = base; i < e; i++)
            red_v4(&g_acc1[dst[i]], ldcg_f4(&g_xs[src[i]]));
    }
    pdl_trigger();
}

// ---------------------------------------------------------------------------
// 4. fused node transform — weights from __constant__ (LDCU path, no LDS):
//    a4 = dinv * acc1          (acc1 already includes self-loop)
//    gs = (relu(a4 W1 + b1) W2) * dinv    — exact reference fma order
//    acc2 INITIALIZED to gs    (layer-2 self-loop term pre-seeded)
__global__ void __launch_bounds__(256) k_mid(int n) {
    pdl_wait();
    int i = blockIdx.x * blockDim.x + threadIdx.x;
    if (i >= n) return;

    float di = g_dinv[i];
    float4 a = g_acc1[i];
    float a0 = di * a.x;
    float a1 = di * a.y;
    float a2 = di * a.z;
    float a3 = di * a.w;

    float o0 = 0.f, o1 = 0.f;
#pragma unroll
    for (int j = 0; j < 64; j++) {
        float h = c_b1[j];
        h = fmaf(a0, c_W1[j],       h);
        h = fmaf(a1, c_W1[64 + j],  h);
        h = fmaf(a2, c_W1[128 + j], h);
        h = fmaf(a3, c_W1[192 + j], h);
        h = fmaxf(h, 0.f);
        o0 = fmaf(h, c_W2[2 * j],     o0);
        o1 = fmaf(h, c_W2[2 * j + 1], o1);
    }
    float2 gs = make_float2(o0 * di, o1 * di);

    g_gs[i]   = gs;
    g_acc2[i] = gs;   // self-loop contribution pre-seeded
    pdl_trigger();
}

// ---------------------------------------------------------------------------
// 5. layer-2 scatter: acc2[dst] += gs[src] — 4 edges/thread
__global__ void __launch_bounds__(256) k_scatter2(const int* __restrict__ src,
                                                  const int* __restrict__ dst, int e) {
    pdl_wait();
    int base = (blockIdx.x * blockDim.x + threadIdx.x) * 4;
    if (base + 4 <= e) {
        int4 s = *(const int4*)(src + base);
        int4 d = *(const int4*)(dst + base);
        float2 v0 = ldcg_f2(&g_gs[s.x]);
        float2 v1 = ldcg_f2(&g_gs[s.y]);
        float2 v2 = ldcg_f2(&g_gs[s.z]);
        float2 v3 = ldcg_f2(&g_gs[s.w]);
        red_v2(&g_acc2[d.x], v0);
        red_v2(&g_acc2[d.y], v1);
        red_v2(&g_acc2[d.z], v2);
        red_v2(&g_acc2[d.w], v3);
    } else {
        for (int i = base; i < e; i++)
            red_v2(&g_acc2[dst[i]], ldcg_f2(&g_gs[src[i]]));
    }
    pdl_trigger();
}

// ---------------------------------------------------------------------------
// 6. final: out = dinv * acc2 + b2 (acc2 already includes self-loop);
//    re-zeroes deg for the next run
__global__ void __launch_bounds__(256) k_final(const float* __restrict__ b2,
                                               float2* __restrict__ out, int n) {
    float bx = __ldg(&b2[0]);
    float by = __ldg(&b2[1]);
    pdl_wait();
    int i = blockIdx.x * blockDim.x + threadIdx.x;
    if (i < n) {
        float di = g_dinv[i];
        float2 a = g_acc2[i];
        out[i] = make_float2(di * a.x + bx, di * a.y + by);
        g_deg[i] = 0.0f;   // self-clean: ready for next invocation/replay
    }
}

// ---------------------------------------------------------------------------
// PDL launch helper
template <typename... Args>
static void pdl_launch(void (*kern)(Args...), int grid, int block,
                       Args... args) {
    cudaLaunchConfig_t cfg = {};
    cfg.gridDim  = dim3(grid, 1, 1);
    cfg.blockDim = dim3(block, 1, 1);
    cfg.dynamicSmemBytes = 0;
    cfg.stream = 0;
    cudaLaunchAttribute attr[1];
    attr[0].id = cudaLaunchAttributeProgrammaticStreamSerialization;
    attr[0].val.programmaticStreamSerializationAllowed = 1;
    cfg.attrs = attr;
    cfg.numAttrs = 1;
    cudaLaunchKernelEx(&cfg, kern, args...);
}

extern "C" void kernel_launch(void* const* d_in, const int* in_sizes, int n_in,
                              void* d_out, int out_size) {
    const float* x  = (const float*)d_in[0];   // [N,4]
    const int*   ei = (const int*)d_in[1];     // [2,E]  int32
    const float* W1 = (const float*)d_in[2];   // [4,64]
    const float* b1 = (const float*)d_in[3];   // [64]
    const float* W2 = (const float*)d_in[4];   // [64,2]
    const float* b2 = (const float*)d_in[5];   // [2]
    float2*      out = (float2*)d_out;         // [N,2]

    const int n = in_sizes[0] / 4;
    const int e = in_sizes[1] / 2;
    const int* src = ei;
    const int* dst = ei + e;

    // Stage weights into __constant__ (async D2D copies — graph-capturable,
    // no allocation). They complete before k_mid by stream order.
    cudaMemcpyToSymbolAsync(c_W1, W1, 256 * sizeof(float), 0,
                            cudaMemcpyDeviceToDevice, 0);
    cudaMemcpyToSymbolAsync(c_b1, b1, 64 * sizeof(float), 0,
                            cudaMemcpyDeviceToDevice, 0);
    cudaMemcpyToSymbolAsync(c_W2, W2, 128 * sizeof(float), 0,
                            cudaMemcpyDeviceToDevice, 0);

    const int T = 256;
    const int gn  = (n + T - 1) / T;
    const int ge4 = ((e + 3) / 4 + T - 1) / T;   // 4 edges/thread

    pdl_launch(k_deg,      ge4, T, dst, e);
    pdl_launch(k_prep,     gn,  T, (const float4*)x, n);
    pdl_launch(k_scatter1, ge4, T, src, dst, e);
    pdl_launch(k_mid,      gn,  T, n);
    pdl_launch(k_scatter2, ge4, T, src, dst, e);
    pdl_launch(k_final,    gn,  T, b2, out, n);
}

// round 16
// speedup vs baseline: 1.0327x; 1.0126x over previous
#include <cuda_runtime.h>
#include <cuda_bf16.h>
#include <stdint.h>

#define NNODE 1000000
#define NEDGE 8000000

// Scratch in __device__ globals (zero-initialized at module load; g_deg is
// re-zeroed by k_final each run -> self-cleaning, no k_zero pass).
__device__ float  g_deg [NNODE];   // in-degree at dst; zeroed in k_final
__device__ float  g_dinv[NNODE];   // rsqrt(deg + 1)
__device__ float4 g_xs  [NNODE];   // x * dinv (gather source for scatter1)
__device__ float4 g_acc1[NNODE];   // layer-1 acc; INIT = xs (self-loop folded in)
__device__ float2 g_gs  [NNODE];   // (relu(.) W2) * dinv (gather source for scatter2)
__device__ float2 g_acc2[NNODE];   // layer-2 acc; INIT = gs (self-loop folded in)

// Weights in constant memory (LDCU uniform path — R15 win).
__constant__ float c_W1[256];   // [4,64] row-major
__constant__ float c_b1[64];
__constant__ float c_W2[128];   // [64,2] row-major

// ---------------------------------------------------------------------------
// PDL intrinsics
__device__ __forceinline__ void pdl_wait() {
    asm volatile("griddepcontrol.wait;" ::: "memory");
}
__device__ __forceinline__ void pdl_trigger() {
    asm volatile("griddepcontrol.launch_dependents;" ::: "memory");
}

__device__ __forceinline__ void red_v4(float4* p, float4 v) {
    asm volatile("red.global.add.v4.f32 [%0], {%1,%2,%3,%4};"
                 :: "l"(p), "f"(v.x), "f"(v.y), "f"(v.z), "f"(v.w) : "memory");
}
__device__ __forceinline__ void red_v2(float2* p, float2 v) {
    asm volatile("red.global.add.v2.f32 [%0], {%1,%2};"
                 :: "l"(p), "f"(v.x), "f"(v.y) : "memory");
}
__device__ __forceinline__ float4 ldcg_f4(const float4* p) { return __ldcg(p); }
__device__ __forceinline__ float2 ldcg_f2(const float2* p) { return __ldcg(p); }

// ---------------------------------------------------------------------------
// 1. in-degree at dst — 4 edges/thread
__global__ void __launch_bounds__(256) k_deg(const int* __restrict__ dst, int e) {
    pdl_wait();
    int base = (blockIdx.x * blockDim.x + threadIdx.x) * 4;
    if (base + 4 <= e) {
        int4 d = *(const int4*)(dst + base);
        atomicAdd(&g_deg[d.x], 1.0f);
        atomicAdd(&g_deg[d.y], 1.0f);
        atomicAdd(&g_deg[d.z], 1.0f);
        atomicAdd(&g_deg[d.w], 1.0f);
    } else {
        for (int i = base; i < e; i++) atomicAdd(&g_deg[dst[i]], 1.0f);
    }
    pdl_trigger();
}

// ---------------------------------------------------------------------------
// 2. dinv + pre-scaled features; acc1 INITIALIZED to xs (self-loop term)
__global__ void __launch_bounds__(256) k_prep(const float4* __restrict__ x, int n) {
    pdl_wait();
    int i = blockIdx.x * blockDim.x + threadIdx.x;
    if (i < n) {
        float di = rsqrtf(g_deg[i] + 1.0f);   // self-loop -> deg >= 1
        g_dinv[i] = di;
        float4 v = x[i];
        v.x *= di; v.y *= di; v.z *= di; v.w *= di;
        g_xs[i]   = v;
        g_acc1[i] = v;   // self-loop contribution pre-seeded
    }
    pdl_trigger();
}

// ---------------------------------------------------------------------------
// 3. layer-1 scatter: acc1[dst] += xs[src] — 4 edges/thread
__global__ void __launch_bounds__(256) k_scatter1(const int* __restrict__ src,
                                                  const int* __restrict__ dst, int e) {
    pdl_wait();
    int base = (blockIdx.x * blockDim.x + threadIdx.x) * 4;
    if (base + 4 <= e) {
        int4 s = *(const int4*)(src + base);
        int4 d = *(const int4*)(dst + base);
        float4 v0 = ldcg_f4(&g_xs[s.x]);
        float4 v1 = ldcg_f4(&g_xs[s.y]);
        float4 v2 = ldcg_f4(&g_xs[s.z]);
        float4 v3 = ldcg_f4(&g_xs[s.w]);
        red_v4(&g_acc1[d.x], v0);
        red_v4(&g_acc1[d.y], v1);
        red_v4(&g_acc1[d.z], v2);
        red_v4(&g_acc1[d.w], v3);
    } else {
        for (int i = base; i < e; i++)
            red_v4(&g_acc1[dst[i]], ldcg_f4(&g_xs[src[i]]));
    }
    pdl_trigger();
}

// ---------------------------------------------------------------------------
// 4. fused node transform — constant weights (LDCU), 2 nodes/thread to
//    amortize the 7 node-invariant weight loads per j over 2 nodes:
//    a4 = dinv * acc1; gs = (relu(a4 W1 + b1) W2) * dinv; acc2 = gs.
//    Per-node fma order identical to the reference.
__global__ void __launch_bounds__(256) k_mid(int nh) {   // nh = n/2
    pdl_wait();
    int i = blockIdx.x * blockDim.x + threadIdx.x;
    if (i >= nh) return;
    int i0 = 2 * i;

    float2 dd = *(const float2*)&g_dinv[i0];
    float4 aA = g_acc1[i0];
    float4 aB = g_acc1[i0 + 1];

    float a0A = dd.x * aA.x, a1A = dd.x * aA.y, a2A = dd.x * aA.z, a3A = dd.x * aA.w;
    float a0B = dd.y * aB.x, a1B = dd.y * aB.y, a2B = dd.y * aB.z, a3B = dd.y * aB.w;

    float o0A = 0.f, o1A = 0.f, o0B = 0.f, o1B = 0.f;
#pragma unroll
    for (int j = 0; j < 64; j++) {
        float w0 = c_W1[j];
        float w1 = c_W1[64 + j];
        float w2 = c_W1[128 + j];
        float w3 = c_W1[192 + j];
        float bb = c_b1[j];
        float c0 = c_W2[2 * j];
        float c1 = c_W2[2 * j + 1];

        float hA = bb;
        hA = fmaf(a0A, w0, hA);
        hA = fmaf(a1A, w1, hA);
        hA = fmaf(a2A, w2, hA);
        hA = fmaf(a3A, w3, hA);
        hA = fmaxf(hA, 0.f);
        o0A = fmaf(hA, c0, o0A);
        o1A = fmaf(hA, c1, o1A);

        float hB = bb;
        hB = fmaf(a0B, w0, hB);
        hB = fmaf(a1B, w1, hB);
        hB = fmaf(a2B, w2, hB);
        hB = fmaf(a3B, w3, hB);
        hB = fmaxf(hB, 0.f);
        o0B = fmaf(hB, c0, o0B);
        o1B = fmaf(hB, c1, o1B);
    }
    float4 gs2 = make_float4(o0A * dd.x, o1A * dd.x, o0B * dd.y, o1B * dd.y);

    *(float4*)&g_gs[i0]   = gs2;   // two consecutive float2 -> one STG.128
    *(float4*)&g_acc2[i0] = gs2;   // self-loop contribution pre-seeded
    pdl_trigger();
}

// ---------------------------------------------------------------------------
// 5. layer-2 scatter: acc2[dst] += gs[src] — 4 edges/thread
__global__ void __launch_bounds__(256) k_scatter2(const int* __restrict__ src,
                                                  const int* __restrict__ dst, int e) {
    pdl_wait();
    int base = (blockIdx.x * blockDim.x + threadIdx.x) * 4;
    if (base + 4 <= e) {
        int4 s = *(const int4*)(src + base);
        int4 d = *(const int4*)(dst + base);
        float2 v0 = ldcg_f2(&g_gs[s.x]);
        float2 v1 = ldcg_f2(&g_gs[s.y]);
        float2 v2 = ldcg_f2(&g_gs[s.z]);
        float2 v3 = ldcg_f2(&g_gs[s.w]);
        red_v2(&g_acc2[d.x], v0);
        red_v2(&g_acc2[d.y], v1);
        red_v2(&g_acc2[d.z], v2);
        red_v2(&g_acc2[d.w], v3);
    } else {
        for (int i = base; i < e; i++)
            red_v2(&g_acc2[dst[i]], ldcg_f2(&g_gs[src[i]]));
    }
    pdl_trigger();
}

// ---------------------------------------------------------------------------
// 6. final: out = dinv * acc2 + b2 (acc2 already includes self-loop);
//    re-zeroes deg for the next run
__global__ void __launch_bounds__(256) k_final(const float* __restrict__ b2,
                                               float2* __restrict__ out, int n) {
    float bx = __ldg(&b2[0]);
    float by = __ldg(&b2[1]);
    pdl_wait();
    int i = blockIdx.x * blockDim.x + threadIdx.x;
    if (i < n) {
        float di = g_dinv[i];
        float2 a = g_acc2[i];
        out[i] = make_float2(di * a.x + bx, di * a.y + by);
        g_deg[i] = 0.0f;   // self-clean: ready for next invocation/replay
    }
}

// ---------------------------------------------------------------------------
// PDL launch helper
template <typename... Args>
static void pdl_launch(void (*kern)(Args...), int grid, int block,
                       Args... args) {
    cudaLaunchConfig_t cfg = {};
    cfg.gridDim  = dim3(grid, 1, 1);
    cfg.blockDim = dim3(block, 1, 1);
    cfg.dynamicSmemBytes = 0;
    cfg.stream = 0;
    cudaLaunchAttribute attr[1];
    attr[0].id = cudaLaunchAttributeProgrammaticStreamSerialization;
    attr[0].val.programmaticStreamSerializationAllowed = 1;
    cfg.attrs = attr;
    cfg.numAttrs = 1;
    cudaLaunchKernelEx(&cfg, kern, args...);
}

extern "C" void kernel_launch(void* const* d_in, const int* in_sizes, int n_in,
                              void* d_out, int out_size) {
    const float* x  = (const float*)d_in[0];   // [N,4]
    const int*   ei = (const int*)d_in[1];     // [2,E]  int32
    const float* W1 = (const float*)d_in[2];   // [4,64]
    const float* b1 = (const float*)d_in[3];   // [64]
    const float* W2 = (const float*)d_in[4];   // [64,2]
    const float* b2 = (const float*)d_in[5];   // [2]
    float2*      out = (float2*)d_out;         // [N,2]

    const int n = in_sizes[0] / 4;
    const int e = in_sizes[1] / 2;
    const int* src = ei;
    const int* dst = ei + e;

    // Stage weights into __constant__ (async D2D copies — graph-capturable,
    // no allocation). They complete before k_mid by stream order.
    cudaMemcpyToSymbolAsync(c_W1, W1, 256 * sizeof(float), 0,
                            cudaMemcpyDeviceToDevice, 0);
    cudaMemcpyToSymbolAsync(c_b1, b1, 64 * sizeof(float), 0,
                            cudaMemcpyDeviceToDevice, 0);
    cudaMemcpyToSymbolAsync(c_W2, W2, 128 * sizeof(float), 0,
                            cudaMemcpyDeviceToDevice, 0);

    const int T = 256;
    const int gn  = (n + T - 1) / T;
    const int gnh = (n / 2 + T - 1) / T;         // node pairs (k_mid)
    const int ge4 = ((e + 3) / 4 + T - 1) / T;   // 4 edges/thread

    pdl_launch(k_deg,      ge4, T, dst, e);
    pdl_launch(k_prep,     gn,  T, (const float4*)x, n);
    pdl_launch(k_scatter1, ge4, T, src, dst, e);
    pdl_launch(k_mid,      gnh, T, n / 2);
    pdl_launch(k_scatter2, ge4, T, src, dst, e);
    pdl_launch(k_final,    gn,  T, b2, out, n);
}